// round 14
// baseline (speedup 1.0000x reference)
#include <cuda_runtime.h>
#include <cuda_fp16.h>
#include <math.h>

// ---------------------------------------------------------------------------
// Persistent kernel, 1184 blocks (8/SM, 32 regs, occ ~100%), 4 grid barriers.
// R8 structure; attention split 32 qunits x 37 slices, 2 queries/thread.
// A: conv partials (blk 0..63) || token pre-pass xr/Xl (blk 64..127)
// B: warp-shuffle reduce partials -> g_pf (blk 0..255)
// C: sample pf + ABC (blk 0..63)
// D: rank-2 attention, f16x2 tanh (all 1184, one unit each)
// E: epilogue (blk 0..63)
// ---------------------------------------------------------------------------
#define NBLK   1184
#define NTHR   256
#define M_TOK  16384
#define TN     8192
#define NSLICE 37
#define SLICE_LEN 222      // 37*222 >= 8192

__device__ float  g_pf_part[2048 * 32];        // [out][chunk] transposed
__device__ float  g_pf[2048];                  // [b*256+pix][j]
__device__ float4 g_Xl[M_TOK];                 // LSTM output per token
__device__ float4 g_ABC[M_TOK];                // (A,B,C,·) per query
__device__ float2 g_XR[M_TOK];                 // xr per token
__device__ float2 g_xrsum[64];                 // per-block Σxr
__device__ float4 g_att[NSLICE * M_TOK];       // (S0,S1,S2,·) partials
__device__ unsigned long long g_barc;          // barrier ticket counter

using u64 = unsigned long long;
__device__ __forceinline__ u64 pack2(float lo, float hi) {
    u64 r; asm("mov.b64 %0,{%1,%2};" : "=l"(r) : "f"(lo), "f"(hi)); return r;
}
__device__ __forceinline__ void unpack2(u64 v, float& lo, float& hi) {
    asm("mov.b64 {%0,%1},%2;" : "=f"(lo), "=f"(hi) : "l"(v));
}
__device__ __forceinline__ u64 fma2(u64 a, u64 b, u64 c) {
    u64 d; asm("fma.rn.f32x2 %0,%1,%2,%3;" : "=l"(d) : "l"(a), "l"(b), "l"(c)); return d;
}
__device__ __forceinline__ u64 add2(u64 a, u64 b) {
    u64 d; asm("add.rn.f32x2 %0,%1,%2;" : "=l"(d) : "l"(a), "l"(b)); return d;
}
__device__ __forceinline__ u64 tanh2(float l0, float l1) {   // 1 MUFU, 2 tanhs
    unsigned h;
    asm("cvt.rn.f16x2.f32 %0,%1,%2;" : "=r"(h) : "f"(l1), "f"(l0));
    asm("tanh.approx.f16x2 %0,%0;" : "+r"(h));
    const __half2 th = *reinterpret_cast<const __half2*>(&h);
    return pack2(__low2float(th), __high2float(th));
}
__device__ __forceinline__ float tanha(float x) {
    float r; asm("tanh.approx.f32 %0,%1;" : "=f"(r) : "f"(x)); return r;
}
__device__ __forceinline__ float sigf(float x) {
    return __fdividef(1.f, 1.f + __expf(-x));
}

__device__ __forceinline__ void gridbar() {
    __syncthreads();
    if (threadIdx.x == 0) {
        __threadfence();
        unsigned long long ticket = atomicAdd(&g_barc, 1ULL);
        unsigned long long target = (ticket / NBLK + 1ULL) * (unsigned long long)NBLK;
        unsigned long long v;
        do {
            asm volatile("ld.global.acquire.gpu.u64 %0,[%1];" : "=l"(v) : "l"(&g_barc));
        } while (v < target);
    }
    __syncthreads();
}

// ---------------------------------------------------------------------------
__global__ void __launch_bounds__(NTHR, 8) k_fused(
    const float* __restrict__ x,
    const float* __restrict__ metadata,
    const float* __restrict__ w_ih, const float* __restrict__ b_ih,
    const float* __restrict__ b_hh,
    const float* __restrict__ fc_w,  const float* __restrict__ fc_b,
    const float* __restrict__ fc2_w, const float* __restrict__ fc2_b,
    const float* __restrict__ fc3_w, const float* __restrict__ fc3_b,
    const float* __restrict__ comp_w, const float* __restrict__ comp_b,
    const float* __restrict__ vf_w,  const float* __restrict__ vf_b,
    const float* __restrict__ fcout_w, const float* __restrict__ fcout_b,
    float* __restrict__ out)
{
    __shared__ __align__(16) char shraw[SLICE_LEN * 16 + 64];
    const int tid  = threadIdx.x;
    const int blk  = blockIdx.x;
    const int gtid = blk * NTHR + tid;

    // ===== Phase A ==========================================================
    if (blk < 64) {
        // conv partials: chunk = blk>>1 (64 in-ch), b = blk&1
        const int chunk = blk >> 1;
        const int b     = blk & 1;
        const int c0    = chunk * 64;
        float* sWp = (float*)shraw;          // [j4][cl64]
        {
            const int j = tid >> 6, cl = tid & 63;   // all 256 threads
            const float* vw = vf_w + j * 36 + 4;
            float s = 0.f;
#pragma unroll
            for (int c = 0; c < 32; ++c)
                s = fmaf(__ldg(vw + c), __ldg(comp_w + c * 2048 + c0 + cl), s);
            sWp[tid] = s;
        }
        __syncthreads();

        float a0 = 0.f, a1 = 0.f, a2 = 0.f, a3 = 0.f;
        const float* mp = metadata + ((size_t)b * 2048 + c0) * 256 + tid;
#pragma unroll 8
        for (int cl = 0; cl < 64; ++cl) {
            const float mv = __ldg(mp + cl * 256);
            a0 = fmaf(mv, sWp[cl],       a0);
            a1 = fmaf(mv, sWp[64 + cl],  a1);
            a2 = fmaf(mv, sWp[128 + cl], a2);
            a3 = fmaf(mv, sWp[192 + cl], a3);
        }
        const int o = (b * 256 + tid) * 4;   // transposed [o][chunk]
        g_pf_part[(o + 0) * 32 + chunk] = a0;
        g_pf_part[(o + 1) * 32 + chunk] = a1;
        g_pf_part[(o + 2) * 32 + chunk] = a2;
        g_pf_part[(o + 3) * 32 + chunk] = a3;
        __syncthreads();
    } else if (blk < 128) {
        // token pre-pass: xr + LSTM
        const int tb = blk - 64;             // 0..63
        const int m = tb * NTHR + tid;
        const int b = m >> 13;
        const int q = m & 8191;
        const int t = q >> 7;

        const float px = __ldg(x + b * 16384 + q);
        const float py = __ldg(x + b * 16384 + 8192 + q);
        const float xr0 = px + __sinf((float)t);
        const float xr1 = py + __cosf((float)t);

        float Xl[4];
#pragma unroll
        for (int j = 0; j < 4; ++j) {
            float gi = __ldg(w_ih + 2*j)      * xr0 + __ldg(w_ih + 2*j+1)      * xr1 + __ldg(b_ih + j)      + __ldg(b_hh + j);
            float gg = __ldg(w_ih + 2*(8+j))  * xr0 + __ldg(w_ih + 2*(8+j)+1)  * xr1 + __ldg(b_ih + 8 + j)  + __ldg(b_hh + 8 + j);
            float go = __ldg(w_ih + 2*(12+j)) * xr0 + __ldg(w_ih + 2*(12+j)+1) * xr1 + __ldg(b_ih + 12 + j) + __ldg(b_hh + 12 + j);
            float cst = sigf(gi) * tanha(gg);
            Xl[j] = sigf(go) * tanha(cst);
        }
        g_Xl[m] = make_float4(Xl[0], Xl[1], Xl[2], Xl[3]);
        g_XR[m] = make_float2(xr0, xr1);

        float2* sh2 = (float2*)shraw;
        sh2[tid] = make_float2(xr0, xr1);
        __syncthreads();
        for (int off = 128; off > 0; off >>= 1) {
            if (tid < off) {
                sh2[tid].x += sh2[tid + off].x;
                sh2[tid].y += sh2[tid + off].y;
            }
            __syncthreads();
        }
        if (tid == 0) g_xrsum[tb] = sh2[0];
        __syncthreads();
    }
    gridbar();

    // ===== Phase B: pf reduce (blk 0..255, coalesced) =======================
    if (blk < 256) {
        const int o    = blk * 8 + (tid >> 5);   // 0..2047
        const int lane = tid & 31;               // = chunk (coalesced)
        const int j    = o & 3;
        float v = g_pf_part[o * 32 + lane]
                + __ldg(vf_w + j * 36 + 4 + lane) * __ldg(comp_b + lane);
#pragma unroll
        for (int off = 16; off > 0; off >>= 1)
            v += __shfl_down_sync(0xffffffffu, v, off);
        if (lane == 0) g_pf[o] = v;
    }
    gridbar();

    // ===== Phase C: sample pf + ABC (blocks 0..63) ==========================
    if (blk < 64) {
        const int m = gtid;
        const int b = m >> 13;
        const int q = m & 8191;

        const float px = __ldg(x + b * 16384 + q);
        const float py = __ldg(x + b * 16384 + 8192 + q);
        const float4 Xlv = g_Xl[m];
        const float Xl[4] = { Xlv.x, Xlv.y, Xlv.z, Xlv.w };

        const float ix = px * (1.f / 32.f) - 0.5f;
        const float iy = py * (1.f / 32.f) - 0.5f;
        const float fx0 = floorf(ix), fy0 = floorf(iy);
        const float wx = ix - fx0, wy = iy - fy0;
        const int x0i = (int)fx0, y0i = (int)fy0;

        float lp0 = 0.f, lp1 = 0.f, lp2 = 0.f, lp3 = 0.f;
        const float cw[4] = { (1.f-wy)*(1.f-wx), (1.f-wy)*wx, wy*(1.f-wx), wy*wx };
        const int   cxx[4] = { x0i, x0i + 1, x0i,     x0i + 1 };
        const int   cyy[4] = { y0i, y0i,     y0i + 1, y0i + 1 };
        const float4* pf = (const float4*)g_pf;
#pragma unroll
        for (int cn = 0; cn < 4; ++cn) {
            const int xx = cxx[cn], yy = cyy[cn];
            if (xx >= 0 && xx < 16 && yy >= 0 && yy < 16) {
                const float4 v = pf[b * 256 + yy * 16 + xx];
                const float w = cw[cn];
                lp0 = fmaf(w, v.x, lp0);
                lp1 = fmaf(w, v.y, lp1);
                lp2 = fmaf(w, v.z, lp2);
                lp3 = fmaf(w, v.w, lp3);
            }
        }

        float Xp[4] = { lp0, lp1, lp2, lp3 };
#pragma unroll
        for (int j = 0; j < 4; ++j) {
            float s = Xp[j] + __ldg(vf_b + j);
#pragma unroll
            for (int k = 0; k < 4; ++k)
                s = fmaf(__ldg(vf_w + j*36 + k), Xl[k], s);
            Xp[j] = s;
        }

        float A = 0.f, Bv = 0.f, Cv = 0.f;
#pragma unroll
        for (int d = 0; d < 8; ++d) {
            float qd = __ldg(fc_b + d);
#pragma unroll
            for (int k = 0; k < 4; ++k) qd = fmaf(__ldg(fc_w + d*4 + k), Xp[k], qd);
            A  = fmaf(qd, __ldg(fc2_w + 2*d),     A);
            Bv = fmaf(qd, __ldg(fc2_w + 2*d + 1), Bv);
            Cv = fmaf(qd, __ldg(fc2_b + d),       Cv);
        }
        g_ABC[m] = make_float4(0.5f * A, 0.5f * Bv, 0.5f * Cv, 0.f);
    }
    gridbar();

    // ===== Phase D: attention — one unit per block (32 qunits x 37) ========
    {
        const int qunit = blk / NSLICE;          // 0..31 (512 queries each)
        const int ksl   = blk - qunit * NSLICE;  // 0..36
        const int qb    = qunit >> 4;            // batch
        const int k0    = ksl * SLICE_LEN;
        const int klen  = min(SLICE_LEN, TN - k0);

        u64* s_x0 = (u64*)shraw;                 // duplicated xr0
        u64* s_x1 = s_x0 + SLICE_LEN;            // duplicated xr1
        for (int i = tid; i < klen; i += NTHR) {
            float2 v = g_XR[qb * TN + k0 + i];
            s_x0[i] = pack2(v.x, v.x);
            s_x1[i] = pack2(v.y, v.y);
        }
        __syncthreads();

        const int m0 = qunit * 512 + tid * 2;    // 2 queries = 1 u64 slot
        u64 A, Bv, C, S0, S1, S2;
        {
            float4 a0 = g_ABC[m0];
            float4 a1 = g_ABC[m0 + 1];
            A  = pack2(a0.x, a1.x);
            Bv = pack2(a0.y, a1.y);
            C  = pack2(a0.z, a1.z);
            S0 = 0ull; S1 = 0ull; S2 = 0ull;
        }

#pragma unroll 4
        for (int k = 0; k < klen; ++k) {
            const u64 x0 = s_x0[k];
            const u64 x1 = s_x1[k];
            u64 l = fma2(A, x0, fma2(Bv, x1, C));
            float l0, l1; unpack2(l, l0, l1);
            const u64 t = tanh2(l0, l1);
            S0 = add2(S0, t);
            S1 = fma2(t, x0, S1);
            S2 = fma2(t, x1, S2);
        }

        float4* op = g_att + (size_t)ksl * M_TOK + m0;
        float a0, a1, b0, b1, c0, c1;
        unpack2(S0, a0, a1); unpack2(S1, b0, b1); unpack2(S2, c0, c1);
        op[0] = make_float4(a0, b0, c0, 0.f);
        op[1] = make_float4(a1, b1, c1, 0.f);
    }
    gridbar();

    // ===== Phase E: epilogue (blocks 0..63) =================================
    if (blk < 64) {
        const int m = gtid;
        const int b = m >> 13;

        float S0 = 0.f, S1 = 0.f, S2 = 0.f;
#pragma unroll
        for (int ks = 0; ks < NSLICE; ++ks) {
            float4 p = g_att[(size_t)ks * M_TOK + m];
            S0 += p.x; S1 += p.y; S2 += p.z;
        }
        float sx0 = 0.f, sx1 = 0.f;
#pragma unroll
        for (int i = 0; i < 32; ++i) {
            float2 v = g_xrsum[b * 32 + i];
            sx0 += v.x; sx1 += v.y;
        }
        const float f1 = 0.5f * (sx0 + S1);
        const float f2 = 0.5f * (sx1 + S2);
        const float f0 = 0.5f * ((float)TN + S0);

        float r0 = __ldg(fcout_b + 0);
        float r1 = __ldg(fcout_b + 1);
#pragma unroll
        for (int d = 0; d < 8; ++d) {
            float o = f1 * __ldg(fc3_w + 2*d) + f2 * __ldg(fc3_w + 2*d + 1)
                    + f0 * __ldg(fc3_b + d);
            o = (o > 0.5f) ? o : 0.f;
            r0 = fmaf(__ldg(fcout_w + d),     o, r0);
            r1 = fmaf(__ldg(fcout_w + 8 + d), o, r1);
        }
        const int q = m & 8191;
        out[b * 16384 + q]        = r0;
        out[b * 16384 + 8192 + q] = r1;
    }
}

// ---------------------------------------------------------------------------
extern "C" void kernel_launch(void* const* d_in, const int* in_sizes, int n_in,
                              void* d_out, int out_size)
{
    const float* x        = (const float*)d_in[0];
    const float* metadata = (const float*)d_in[1];
    const float* w_ih     = (const float*)d_in[2];
    const float* b_ih     = (const float*)d_in[4];
    const float* b_hh     = (const float*)d_in[5];
    const float* fc_w     = (const float*)d_in[6];
    const float* fc_b     = (const float*)d_in[7];
    const float* fc2_w    = (const float*)d_in[8];
    const float* fc2_b    = (const float*)d_in[9];
    const float* fc3_w    = (const float*)d_in[10];
    const float* fc3_b    = (const float*)d_in[11];
    const float* comp_w   = (const float*)d_in[12];
    const float* comp_b   = (const float*)d_in[13];
    const float* vf_w     = (const float*)d_in[14];
    const float* vf_b     = (const float*)d_in[15];
    const float* fcout_w  = (const float*)d_in[16];
    const float* fcout_b  = (const float*)d_in[17];
    float* out = (float*)d_out;

    k_fused<<<NBLK, NTHR>>>(x, metadata, w_ih, b_ih, b_hh, fc_w, fc_b,
                            fc2_w, fc2_b, fc3_w, fc3_b, comp_w, comp_b,
                            vf_w, vf_b, fcout_w, fcout_b, out);
}

// round 15
// speedup vs baseline: 1.1286x; 1.1286x over previous
#include <cuda_runtime.h>
#include <cuda_fp16.h>
#include <math.h>

// ---------------------------------------------------------------------------
// 5 graph-captured kernels (stream-ordered, no software barriers).
// K1: conv partials (blk 0..63) || token pre-pass (blk 64..127)
// K2: warp-shuffle pf reduce (256 blocks, coalesced)
// K3: sample pf + ABC (64 blocks)
// K4: rank-2 attention, f16x2 tanh (592 blocks, 4 q/thread)  [R8 phase D]
// K5: epilogue (64 blocks)
// ---------------------------------------------------------------------------
#define NTHR   256
#define M_TOK  16384
#define TN     8192
#define NSLICE 37
#define SLICE_LEN 222      // 37*222 >= 8192

__device__ float  g_pf_part[2048 * 32];        // [out][chunk] transposed
__device__ float  g_pf[2048];                  // [b*256+pix][j]
__device__ float4 g_Xl[M_TOK];                 // LSTM output per token
__device__ float4 g_ABC[M_TOK];                // (A,B,C,·) per query
__device__ float2 g_XR[M_TOK];                 // xr per token
__device__ float2 g_xrsum[64];                 // per-block Σxr
__device__ float4 g_att[NSLICE * M_TOK];       // (S0,S1,S2,·) partials

using u64 = unsigned long long;
__device__ __forceinline__ u64 pack2(float lo, float hi) {
    u64 r; asm("mov.b64 %0,{%1,%2};" : "=l"(r) : "f"(lo), "f"(hi)); return r;
}
__device__ __forceinline__ void unpack2(u64 v, float& lo, float& hi) {
    asm("mov.b64 {%0,%1},%2;" : "=f"(lo), "=f"(hi) : "l"(v));
}
__device__ __forceinline__ u64 fma2(u64 a, u64 b, u64 c) {
    u64 d; asm("fma.rn.f32x2 %0,%1,%2,%3;" : "=l"(d) : "l"(a), "l"(b), "l"(c)); return d;
}
__device__ __forceinline__ u64 add2(u64 a, u64 b) {
    u64 d; asm("add.rn.f32x2 %0,%1,%2;" : "=l"(d) : "l"(a), "l"(b)); return d;
}
__device__ __forceinline__ u64 tanh2(float l0, float l1) {   // 1 MUFU, 2 tanhs
    unsigned h;
    asm("cvt.rn.f16x2.f32 %0,%1,%2;" : "=r"(h) : "f"(l1), "f"(l0));
    asm("tanh.approx.f16x2 %0,%0;" : "+r"(h));
    const __half2 th = *reinterpret_cast<const __half2*>(&h);
    return pack2(__low2float(th), __high2float(th));
}
__device__ __forceinline__ float tanha(float x) {
    float r; asm("tanh.approx.f32 %0,%1;" : "=f"(r) : "f"(x)); return r;
}
__device__ __forceinline__ float sigf(float x) {
    return __fdividef(1.f, 1.f + __expf(-x));
}

// ===========================================================================
// K1: conv partials (blocks 0..63) || token pre-pass (blocks 64..127)
// ===========================================================================
__global__ void __launch_bounds__(NTHR) k1_conv_tokens(
    const float* __restrict__ x,
    const float* __restrict__ metadata,
    const float* __restrict__ w_ih, const float* __restrict__ b_ih,
    const float* __restrict__ b_hh,
    const float* __restrict__ comp_w,
    const float* __restrict__ vf_w)
{
    __shared__ __align__(16) float sh[1024];
    const int tid = threadIdx.x;
    const int blk = blockIdx.x;

    if (blk < 64) {
        const int chunk = blk >> 1;
        const int b     = blk & 1;
        const int c0    = chunk * 64;
        {
            const int j = tid >> 6, cl = tid & 63;   // all 256 threads
            const float* vw = vf_w + j * 36 + 4;
            float s = 0.f;
#pragma unroll
            for (int c = 0; c < 32; ++c)
                s = fmaf(__ldg(vw + c), __ldg(comp_w + c * 2048 + c0 + cl), s);
            sh[tid] = s;
        }
        __syncthreads();

        float a0 = 0.f, a1 = 0.f, a2 = 0.f, a3 = 0.f;
        const float* mp = metadata + ((size_t)b * 2048 + c0) * 256 + tid;
#pragma unroll 8
        for (int cl = 0; cl < 64; ++cl) {
            const float mv = __ldg(mp + cl * 256);
            a0 = fmaf(mv, sh[cl],       a0);
            a1 = fmaf(mv, sh[64 + cl],  a1);
            a2 = fmaf(mv, sh[128 + cl], a2);
            a3 = fmaf(mv, sh[192 + cl], a3);
        }
        const int o = (b * 256 + tid) * 4;   // transposed [o][chunk]
        g_pf_part[(o + 0) * 32 + chunk] = a0;
        g_pf_part[(o + 1) * 32 + chunk] = a1;
        g_pf_part[(o + 2) * 32 + chunk] = a2;
        g_pf_part[(o + 3) * 32 + chunk] = a3;
    } else {
        const int tb = blk - 64;             // 0..63
        const int m = tb * NTHR + tid;
        const int b = m >> 13;
        const int q = m & 8191;
        const int t = q >> 7;

        const float px = __ldg(x + b * 16384 + q);
        const float py = __ldg(x + b * 16384 + 8192 + q);
        const float xr0 = px + __sinf((float)t);
        const float xr1 = py + __cosf((float)t);

        float Xl[4];
#pragma unroll
        for (int j = 0; j < 4; ++j) {
            float gi = __ldg(w_ih + 2*j)      * xr0 + __ldg(w_ih + 2*j+1)      * xr1 + __ldg(b_ih + j)      + __ldg(b_hh + j);
            float gg = __ldg(w_ih + 2*(8+j))  * xr0 + __ldg(w_ih + 2*(8+j)+1)  * xr1 + __ldg(b_ih + 8 + j)  + __ldg(b_hh + 8 + j);
            float go = __ldg(w_ih + 2*(12+j)) * xr0 + __ldg(w_ih + 2*(12+j)+1) * xr1 + __ldg(b_ih + 12 + j) + __ldg(b_hh + 12 + j);
            float cst = sigf(gi) * tanha(gg);
            Xl[j] = sigf(go) * tanha(cst);
        }
        g_Xl[m] = make_float4(Xl[0], Xl[1], Xl[2], Xl[3]);
        g_XR[m] = make_float2(xr0, xr1);

        float2* sh2 = (float2*)sh;
        sh2[tid] = make_float2(xr0, xr1);
        __syncthreads();
        for (int off = 128; off > 0; off >>= 1) {
            if (tid < off) {
                sh2[tid].x += sh2[tid + off].x;
                sh2[tid].y += sh2[tid + off].y;
            }
            __syncthreads();
        }
        if (tid == 0) g_xrsum[tb] = sh2[0];
    }
}

// ===========================================================================
// K2: pf reduce (256 blocks, coalesced)
// ===========================================================================
__global__ void __launch_bounds__(NTHR) k2_reduce(
    const float* __restrict__ comp_b, const float* __restrict__ vf_w)
{
    const int o    = blockIdx.x * 8 + (threadIdx.x >> 5);   // 0..2047
    const int lane = threadIdx.x & 31;                      // = chunk
    const int j    = o & 3;
    float v = g_pf_part[o * 32 + lane]
            + __ldg(vf_w + j * 36 + 4 + lane) * __ldg(comp_b + lane);
#pragma unroll
    for (int off = 16; off > 0; off >>= 1)
        v += __shfl_down_sync(0xffffffffu, v, off);
    if (lane == 0) g_pf[o] = v;
}

// ===========================================================================
// K3: sample pf + ABC (64 blocks)
// ===========================================================================
__global__ void __launch_bounds__(NTHR) k3_abc(
    const float* __restrict__ x,
    const float* __restrict__ fc_w,  const float* __restrict__ fc_b,
    const float* __restrict__ fc2_w, const float* __restrict__ fc2_b,
    const float* __restrict__ vf_w,  const float* __restrict__ vf_b)
{
    const int m = blockIdx.x * NTHR + threadIdx.x;
    const int b = m >> 13;
    const int q = m & 8191;

    const float px = __ldg(x + b * 16384 + q);
    const float py = __ldg(x + b * 16384 + 8192 + q);
    const float4 Xlv = g_Xl[m];
    const float Xl[4] = { Xlv.x, Xlv.y, Xlv.z, Xlv.w };

    const float ix = px * (1.f / 32.f) - 0.5f;
    const float iy = py * (1.f / 32.f) - 0.5f;
    const float fx0 = floorf(ix), fy0 = floorf(iy);
    const float wx = ix - fx0, wy = iy - fy0;
    const int x0i = (int)fx0, y0i = (int)fy0;

    float lp0 = 0.f, lp1 = 0.f, lp2 = 0.f, lp3 = 0.f;
    const float cw[4] = { (1.f-wy)*(1.f-wx), (1.f-wy)*wx, wy*(1.f-wx), wy*wx };
    const int   cxx[4] = { x0i, x0i + 1, x0i,     x0i + 1 };
    const int   cyy[4] = { y0i, y0i,     y0i + 1, y0i + 1 };
    const float4* pf = (const float4*)g_pf;
#pragma unroll
    for (int cn = 0; cn < 4; ++cn) {
        const int xx = cxx[cn], yy = cyy[cn];
        if (xx >= 0 && xx < 16 && yy >= 0 && yy < 16) {
            const float4 v = pf[b * 256 + yy * 16 + xx];
            const float w = cw[cn];
            lp0 = fmaf(w, v.x, lp0);
            lp1 = fmaf(w, v.y, lp1);
            lp2 = fmaf(w, v.z, lp2);
            lp3 = fmaf(w, v.w, lp3);
        }
    }

    float Xp[4] = { lp0, lp1, lp2, lp3 };
#pragma unroll
    for (int j = 0; j < 4; ++j) {
        float s = Xp[j] + __ldg(vf_b + j);
#pragma unroll
        for (int k = 0; k < 4; ++k)
            s = fmaf(__ldg(vf_w + j*36 + k), Xl[k], s);
        Xp[j] = s;
    }

    float A = 0.f, Bv = 0.f, Cv = 0.f;
#pragma unroll
    for (int d = 0; d < 8; ++d) {
        float qd = __ldg(fc_b + d);
#pragma unroll
        for (int k = 0; k < 4; ++k) qd = fmaf(__ldg(fc_w + d*4 + k), Xp[k], qd);
        A  = fmaf(qd, __ldg(fc2_w + 2*d),     A);
        Bv = fmaf(qd, __ldg(fc2_w + 2*d + 1), Bv);
        Cv = fmaf(qd, __ldg(fc2_b + d),       Cv);
    }
    g_ABC[m] = make_float4(0.5f * A, 0.5f * Bv, 0.5f * Cv, 0.f);
}

// ===========================================================================
// K4: attention (592 blocks = 16 qunits x 37 slices, 4 queries/thread)
// ===========================================================================
__global__ void __launch_bounds__(NTHR, 4) k4_attn()
{
    __shared__ __align__(16) char shraw[SLICE_LEN * 16 + 64];
    const int tid = threadIdx.x;
    const int blk = blockIdx.x;

    const int qunit = blk / NSLICE;          // 0..15 (1024 queries each)
    const int ksl   = blk - qunit * NSLICE;  // 0..36
    const int qb    = qunit >> 3;
    const int k0    = ksl * SLICE_LEN;
    const int klen  = min(SLICE_LEN, TN - k0);

    u64* s_x0 = (u64*)shraw;                 // duplicated xr0
    u64* s_x1 = s_x0 + SLICE_LEN;            // duplicated xr1
    for (int i = tid; i < klen; i += NTHR) {
        float2 v = g_XR[qb * TN + k0 + i];
        s_x0[i] = pack2(v.x, v.x);
        s_x1[i] = pack2(v.y, v.y);
    }
    __syncthreads();

    const int m0 = qunit * 1024 + tid * 4;
    u64 A[2], Bv[2], C[2], S0[2], S1[2], S2[2];
#pragma unroll
    for (int p = 0; p < 2; ++p) {
        float4 a0 = g_ABC[m0 + 2*p];
        float4 a1 = g_ABC[m0 + 2*p + 1];
        A[p]  = pack2(a0.x, a1.x);
        Bv[p] = pack2(a0.y, a1.y);
        C[p]  = pack2(a0.z, a1.z);
        S0[p] = 0ull; S1[p] = 0ull; S2[p] = 0ull;
    }

#pragma unroll 2
    for (int k = 0; k < klen; ++k) {
        const u64 x0 = s_x0[k];
        const u64 x1 = s_x1[k];
#pragma unroll
        for (int p = 0; p < 2; ++p) {
            u64 l = fma2(A[p], x0, fma2(Bv[p], x1, C[p]));
            float l0, l1; unpack2(l, l0, l1);
            const u64 t = tanh2(l0, l1);
            S0[p] = add2(S0[p], t);
            S1[p] = fma2(t, x0, S1[p]);
            S2[p] = fma2(t, x1, S2[p]);
        }
    }

    float4* op = g_att + (size_t)ksl * M_TOK + m0;
#pragma unroll
    for (int p = 0; p < 2; ++p) {
        float a0, a1, b0, b1, c0, c1;
        unpack2(S0[p], a0, a1); unpack2(S1[p], b0, b1); unpack2(S2[p], c0, c1);
        op[2*p]     = make_float4(a0, b0, c0, 0.f);
        op[2*p + 1] = make_float4(a1, b1, c1, 0.f);
    }
}

// ===========================================================================
// K5: epilogue (64 blocks)
// ===========================================================================
__global__ void __launch_bounds__(NTHR) k5_epilogue(
    float* __restrict__ out,
    const float* __restrict__ fc3_w, const float* __restrict__ fc3_b,
    const float* __restrict__ fcout_w, const float* __restrict__ fcout_b)
{
    const int m = blockIdx.x * NTHR + threadIdx.x;
    const int b = m >> 13;

    float S0 = 0.f, S1 = 0.f, S2 = 0.f;
#pragma unroll
    for (int ks = 0; ks < NSLICE; ++ks) {
        float4 p = g_att[(size_t)ks * M_TOK + m];
        S0 += p.x; S1 += p.y; S2 += p.z;
    }
    float sx0 = 0.f, sx1 = 0.f;
#pragma unroll
    for (int i = 0; i < 32; ++i) {
        float2 v = g_xrsum[b * 32 + i];
        sx0 += v.x; sx1 += v.y;
    }
    const float f1 = 0.5f * (sx0 + S1);
    const float f2 = 0.5f * (sx1 + S2);
    const float f0 = 0.5f * ((float)TN + S0);

    float r0 = __ldg(fcout_b + 0);
    float r1 = __ldg(fcout_b + 1);
#pragma unroll
    for (int d = 0; d < 8; ++d) {
        float o = f1 * __ldg(fc3_w + 2*d) + f2 * __ldg(fc3_w + 2*d + 1)
                + f0 * __ldg(fc3_b + d);
        o = (o > 0.5f) ? o : 0.f;
        r0 = fmaf(__ldg(fcout_w + d),     o, r0);
        r1 = fmaf(__ldg(fcout_w + 8 + d), o, r1);
    }
    const int q = m & 8191;
    out[b * 16384 + q]        = r0;
    out[b * 16384 + 8192 + q] = r1;
}

// ---------------------------------------------------------------------------
extern "C" void kernel_launch(void* const* d_in, const int* in_sizes, int n_in,
                              void* d_out, int out_size)
{
    const float* x        = (const float*)d_in[0];
    const float* metadata = (const float*)d_in[1];
    const float* w_ih     = (const float*)d_in[2];
    const float* b_ih     = (const float*)d_in[4];
    const float* b_hh     = (const float*)d_in[5];
    const float* fc_w     = (const float*)d_in[6];
    const float* fc_b     = (const float*)d_in[7];
    const float* fc2_w    = (const float*)d_in[8];
    const float* fc2_b    = (const float*)d_in[9];
    const float* fc3_w    = (const float*)d_in[10];
    const float* fc3_b    = (const float*)d_in[11];
    const float* comp_w   = (const float*)d_in[12];
    const float* comp_b   = (const float*)d_in[13];
    const float* vf_w     = (const float*)d_in[14];
    const float* vf_b     = (const float*)d_in[15];
    const float* fcout_w  = (const float*)d_in[16];
    const float* fcout_b  = (const float*)d_in[17];
    float* out = (float*)d_out;

    k1_conv_tokens<<<128, NTHR>>>(x, metadata, w_ih, b_ih, b_hh, comp_w, vf_w);
    k2_reduce<<<256, NTHR>>>(comp_b, vf_w);
    k3_abc<<<64, NTHR>>>(x, fc_w, fc_b, fc2_w, fc2_b, vf_w, vf_b);
    k4_attn<<<592, NTHR>>>();
    k5_epilogue<<<64, NTHR>>>(out, fc3_w, fc3_b, fcout_w, fcout_b);
}

// round 16
// speedup vs baseline: 1.2099x; 1.0721x over previous
#include <cuda_runtime.h>
#include <cuda_fp16.h>
#include <math.h>

// ---------------------------------------------------------------------------
// 5 graph-captured kernels (stream-ordered).
// K1: conv partials (blk 0..63) || token pre-pass (blk 64..127)
// K2: warp-shuffle pf reduce (256 blocks, coalesced)
// K3: sample pf + ABC (64 blocks)
// K4: rank-2 attention, KEY-PACKED f32x2 (2 keys/slot, 4 queries/thread)
// K5: epilogue (64 blocks)
// ---------------------------------------------------------------------------
#define NTHR   256
#define M_TOK  16384
#define TN     8192
#define NSLICE 37
#define SLICE_LEN 222      // 37*222 >= 8192 ; even, and last slice 200 even

__device__ float  g_pf_part[2048 * 32];        // [out][chunk] transposed
__device__ float  g_pf[2048];                  // [b*256+pix][j]
__device__ float4 g_Xl[M_TOK];                 // LSTM output per token
__device__ float4 g_ABC[M_TOK];                // (A,B,C,·) per query
__device__ float2 g_XR[M_TOK];                 // xr per token
__device__ float2 g_xrsum[64];                 // per-block Σxr
__device__ float4 g_att[NSLICE * M_TOK];       // (S0,S1,S2,·) partials

using u64 = unsigned long long;
__device__ __forceinline__ u64 pack2(float lo, float hi) {
    u64 r; asm("mov.b64 %0,{%1,%2};" : "=l"(r) : "f"(lo), "f"(hi)); return r;
}
__device__ __forceinline__ void unpack2(u64 v, float& lo, float& hi) {
    asm("mov.b64 {%0,%1},%2;" : "=f"(lo), "=f"(hi) : "l"(v));
}
__device__ __forceinline__ u64 fma2(u64 a, u64 b, u64 c) {
    u64 d; asm("fma.rn.f32x2 %0,%1,%2,%3;" : "=l"(d) : "l"(a), "l"(b), "l"(c)); return d;
}
__device__ __forceinline__ u64 add2(u64 a, u64 b) {
    u64 d; asm("add.rn.f32x2 %0,%1,%2;" : "=l"(d) : "l"(a), "l"(b)); return d;
}
__device__ __forceinline__ u64 tanh2(float l0, float l1) {   // 1 MUFU, 2 tanhs
    unsigned h;
    asm("cvt.rn.f16x2.f32 %0,%1,%2;" : "=r"(h) : "f"(l1), "f"(l0));
    asm("tanh.approx.f16x2 %0,%0;" : "+r"(h));
    const __half2 th = *reinterpret_cast<const __half2*>(&h);
    return pack2(__low2float(th), __high2float(th));
}
__device__ __forceinline__ float tanha(float x) {
    float r; asm("tanh.approx.f32 %0,%1;" : "=f"(r) : "f"(x)); return r;
}
__device__ __forceinline__ float sigf(float x) {
    return __fdividef(1.f, 1.f + __expf(-x));
}

// ===========================================================================
// K1: conv partials (blocks 0..63) || token pre-pass (blocks 64..127)
// ===========================================================================
__global__ void __launch_bounds__(NTHR) k1_conv_tokens(
    const float* __restrict__ x,
    const float* __restrict__ metadata,
    const float* __restrict__ w_ih, const float* __restrict__ b_ih,
    const float* __restrict__ b_hh,
    const float* __restrict__ comp_w,
    const float* __restrict__ vf_w)
{
    __shared__ __align__(16) float sh[1024];
    const int tid = threadIdx.x;
    const int blk = blockIdx.x;

    if (blk < 64) {
        const int chunk = blk >> 1;
        const int b     = blk & 1;
        const int c0    = chunk * 64;
        {
            const int j = tid >> 6, cl = tid & 63;   // all 256 threads
            const float* vw = vf_w + j * 36 + 4;
            float s = 0.f;
#pragma unroll
            for (int c = 0; c < 32; ++c)
                s = fmaf(__ldg(vw + c), __ldg(comp_w + c * 2048 + c0 + cl), s);
            sh[tid] = s;
        }
        __syncthreads();

        float a0 = 0.f, a1 = 0.f, a2 = 0.f, a3 = 0.f;
        const float* mp = metadata + ((size_t)b * 2048 + c0) * 256 + tid;
#pragma unroll 8
        for (int cl = 0; cl < 64; ++cl) {
            const float mv = __ldg(mp + cl * 256);
            a0 = fmaf(mv, sh[cl],       a0);
            a1 = fmaf(mv, sh[64 + cl],  a1);
            a2 = fmaf(mv, sh[128 + cl], a2);
            a3 = fmaf(mv, sh[192 + cl], a3);
        }
        const int o = (b * 256 + tid) * 4;   // transposed [o][chunk]
        g_pf_part[(o + 0) * 32 + chunk] = a0;
        g_pf_part[(o + 1) * 32 + chunk] = a1;
        g_pf_part[(o + 2) * 32 + chunk] = a2;
        g_pf_part[(o + 3) * 32 + chunk] = a3;
    } else {
        const int tb = blk - 64;             // 0..63
        const int m = tb * NTHR + tid;
        const int b = m >> 13;
        const int q = m & 8191;
        const int t = q >> 7;

        const float px = __ldg(x + b * 16384 + q);
        const float py = __ldg(x + b * 16384 + 8192 + q);
        const float xr0 = px + __sinf((float)t);
        const float xr1 = py + __cosf((float)t);

        float Xl[4];
#pragma unroll
        for (int j = 0; j < 4; ++j) {
            float gi = __ldg(w_ih + 2*j)      * xr0 + __ldg(w_ih + 2*j+1)      * xr1 + __ldg(b_ih + j)      + __ldg(b_hh + j);
            float gg = __ldg(w_ih + 2*(8+j))  * xr0 + __ldg(w_ih + 2*(8+j)+1)  * xr1 + __ldg(b_ih + 8 + j)  + __ldg(b_hh + 8 + j);
            float go = __ldg(w_ih + 2*(12+j)) * xr0 + __ldg(w_ih + 2*(12+j)+1) * xr1 + __ldg(b_ih + 12 + j) + __ldg(b_hh + 12 + j);
            float cst = sigf(gi) * tanha(gg);
            Xl[j] = sigf(go) * tanha(cst);
        }
        g_Xl[m] = make_float4(Xl[0], Xl[1], Xl[2], Xl[3]);
        g_XR[m] = make_float2(xr0, xr1);

        float2* sh2 = (float2*)sh;
        sh2[tid] = make_float2(xr0, xr1);
        __syncthreads();
        for (int off = 128; off > 0; off >>= 1) {
            if (tid < off) {
                sh2[tid].x += sh2[tid + off].x;
                sh2[tid].y += sh2[tid + off].y;
            }
            __syncthreads();
        }
        if (tid == 0) g_xrsum[tb] = sh2[0];
    }
}

// ===========================================================================
// K2: pf reduce (256 blocks, coalesced)
// ===========================================================================
__global__ void __launch_bounds__(NTHR) k2_reduce(
    const float* __restrict__ comp_b, const float* __restrict__ vf_w)
{
    const int o    = blockIdx.x * 8 + (threadIdx.x >> 5);   // 0..2047
    const int lane = threadIdx.x & 31;                      // = chunk
    const int j    = o & 3;
    float v = g_pf_part[o * 32 + lane]
            + __ldg(vf_w + j * 36 + 4 + lane) * __ldg(comp_b + lane);
#pragma unroll
    for (int off = 16; off > 0; off >>= 1)
        v += __shfl_down_sync(0xffffffffu, v, off);
    if (lane == 0) g_pf[o] = v;
}

// ===========================================================================
// K3: sample pf + ABC (64 blocks)
// ===========================================================================
__global__ void __launch_bounds__(NTHR) k3_abc(
    const float* __restrict__ x,
    const float* __restrict__ fc_w,  const float* __restrict__ fc_b,
    const float* __restrict__ fc2_w, const float* __restrict__ fc2_b,
    const float* __restrict__ vf_w,  const float* __restrict__ vf_b)
{
    const int m = blockIdx.x * NTHR + threadIdx.x;
    const int b = m >> 13;
    const int q = m & 8191;

    const float px = __ldg(x + b * 16384 + q);
    const float py = __ldg(x + b * 16384 + 8192 + q);
    const float4 Xlv = g_Xl[m];
    const float Xl[4] = { Xlv.x, Xlv.y, Xlv.z, Xlv.w };

    const float ix = px * (1.f / 32.f) - 0.5f;
    const float iy = py * (1.f / 32.f) - 0.5f;
    const float fx0 = floorf(ix), fy0 = floorf(iy);
    const float wx = ix - fx0, wy = iy - fy0;
    const int x0i = (int)fx0, y0i = (int)fy0;

    float lp0 = 0.f, lp1 = 0.f, lp2 = 0.f, lp3 = 0.f;
    const float cw[4] = { (1.f-wy)*(1.f-wx), (1.f-wy)*wx, wy*(1.f-wx), wy*wx };
    const int   cxx[4] = { x0i, x0i + 1, x0i,     x0i + 1 };
    const int   cyy[4] = { y0i, y0i,     y0i + 1, y0i + 1 };
    const float4* pf = (const float4*)g_pf;
#pragma unroll
    for (int cn = 0; cn < 4; ++cn) {
        const int xx = cxx[cn], yy = cyy[cn];
        if (xx >= 0 && xx < 16 && yy >= 0 && yy < 16) {
            const float4 v = pf[b * 256 + yy * 16 + xx];
            const float w = cw[cn];
            lp0 = fmaf(w, v.x, lp0);
            lp1 = fmaf(w, v.y, lp1);
            lp2 = fmaf(w, v.z, lp2);
            lp3 = fmaf(w, v.w, lp3);
        }
    }

    float Xp[4] = { lp0, lp1, lp2, lp3 };
#pragma unroll
    for (int j = 0; j < 4; ++j) {
        float s = Xp[j] + __ldg(vf_b + j);
#pragma unroll
        for (int k = 0; k < 4; ++k)
            s = fmaf(__ldg(vf_w + j*36 + k), Xl[k], s);
        Xp[j] = s;
    }

    float A = 0.f, Bv = 0.f, Cv = 0.f;
#pragma unroll
    for (int d = 0; d < 8; ++d) {
        float qd = __ldg(fc_b + d);
#pragma unroll
        for (int k = 0; k < 4; ++k) qd = fmaf(__ldg(fc_w + d*4 + k), Xp[k], qd);
        A  = fmaf(qd, __ldg(fc2_w + 2*d),     A);
        Bv = fmaf(qd, __ldg(fc2_w + 2*d + 1), Bv);
        Cv = fmaf(qd, __ldg(fc2_b + d),       Cv);
    }
    g_ABC[m] = make_float4(0.5f * A, 0.5f * Bv, 0.5f * Cv, 0.f);
}

// ===========================================================================
// K4: attention, KEY-PACKED (592 blocks = 16 qunits x 37 slices)
// Each thread: 4 queries, keys processed 2-per-f32x2.
// ===========================================================================
__global__ void __launch_bounds__(NTHR, 4) k4_attn()
{
    __shared__ __align__(16) float s_x0[SLICE_LEN];
    __shared__ __align__(16) float s_x1[SLICE_LEN];
    const int tid = threadIdx.x;
    const int blk = blockIdx.x;

    const int qunit = blk / NSLICE;          // 0..15 (1024 queries each)
    const int ksl   = blk - qunit * NSLICE;  // 0..36
    const int qb    = qunit >> 3;
    const int k0    = ksl * SLICE_LEN;
    const int klen  = min(SLICE_LEN, TN - k0);   // 222 or 200; always even

    for (int i = tid; i < klen; i += NTHR) {
        float2 v = g_XR[qb * TN + k0 + i];
        s_x0[i] = v.x;
        s_x1[i] = v.y;
    }
    __syncthreads();

    const int m0 = qunit * 1024 + tid * 4;
    u64 A[4], Bv[4], C[4], S0[4], S1[4], S2[4];
#pragma unroll
    for (int q = 0; q < 4; ++q) {
        const float4 a = g_ABC[m0 + q];
        A[q]  = pack2(a.x, a.x);             // duplicated coefficients
        Bv[q] = pack2(a.y, a.y);
        C[q]  = pack2(a.z, a.z);
        S0[q] = 0ull; S1[q] = 0ull; S2[q] = 0ull;
    }

    const u64* px0 = (const u64*)s_x0;       // (x0_{2k}, x0_{2k+1})
    const u64* px1 = (const u64*)s_x1;
    const int half = klen >> 1;
#pragma unroll 2
    for (int k = 0; k < half; ++k) {
        const u64 x0 = px0[k];               // one LDS.64 = 2 keys
        const u64 x1 = px1[k];
#pragma unroll
        for (int q = 0; q < 4; ++q) {
            u64 z = fma2(A[q], x0, fma2(Bv[q], x1, C[q]));
            float zl, zh; unpack2(z, zl, zh);
            const u64 t = tanh2(zl, zh);     // 2 keys of this query
            S0[q] = add2(S0[q], t);
            S1[q] = fma2(t, x0, S1[q]);
            S2[q] = fma2(t, x1, S2[q]);
        }
    }

    float4* op = g_att + (size_t)ksl * M_TOK + m0;
#pragma unroll
    for (int q = 0; q < 4; ++q) {
        float a0, a1, b0, b1, c0, c1;
        unpack2(S0[q], a0, a1); unpack2(S1[q], b0, b1); unpack2(S2[q], c0, c1);
        op[q] = make_float4(a0 + a1, b0 + b1, c0 + c1, 0.f);   // fold even/odd
    }
}

// ===========================================================================
// K5: epilogue (64 blocks)
// ===========================================================================
__global__ void __launch_bounds__(NTHR) k5_epilogue(
    float* __restrict__ out,
    const float* __restrict__ fc3_w, const float* __restrict__ fc3_b,
    const float* __restrict__ fcout_w, const float* __restrict__ fcout_b)
{
    const int m = blockIdx.x * NTHR + threadIdx.x;
    const int b = m >> 13;

    float S0 = 0.f, S1 = 0.f, S2 = 0.f;
#pragma unroll
    for (int ks = 0; ks < NSLICE; ++ks) {
        float4 p = g_att[(size_t)ks * M_TOK + m];
        S0 += p.x; S1 += p.y; S2 += p.z;
    }
    float sx0 = 0.f, sx1 = 0.f;
#pragma unroll
    for (int i = 0; i < 32; ++i) {
        float2 v = g_xrsum[b * 32 + i];
        sx0 += v.x; sx1 += v.y;
    }
    const float f1 = 0.5f * (sx0 + S1);
    const float f2 = 0.5f * (sx1 + S2);
    const float f0 = 0.5f * ((float)TN + S0);

    float r0 = __ldg(fcout_b + 0);
    float r1 = __ldg(fcout_b + 1);
#pragma unroll
    for (int d = 0; d < 8; ++d) {
        float o = f1 * __ldg(fc3_w + 2*d) + f2 * __ldg(fc3_w + 2*d + 1)
                + f0 * __ldg(fc3_b + d);
        o = (o > 0.5f) ? o : 0.f;
        r0 = fmaf(__ldg(fcout_w + d),     o, r0);
        r1 = fmaf(__ldg(fcout_w + 8 + d), o, r1);
    }
    const int q = m & 8191;
    out[b * 16384 + q]        = r0;
    out[b * 16384 + 8192 + q] = r1;
}

// ---------------------------------------------------------------------------
extern "C" void kernel_launch(void* const* d_in, const int* in_sizes, int n_in,
                              void* d_out, int out_size)
{
    const float* x        = (const float*)d_in[0];
    const float* metadata = (const float*)d_in[1];
    const float* w_ih     = (const float*)d_in[2];
    const float* b_ih     = (const float*)d_in[4];
    const float* b_hh     = (const float*)d_in[5];
    const float* fc_w     = (const float*)d_in[6];
    const float* fc_b     = (const float*)d_in[7];
    const float* fc2_w    = (const float*)d_in[8];
    const float* fc2_b    = (const float*)d_in[9];
    const float* fc3_w    = (const float*)d_in[10];
    const float* fc3_b    = (const float*)d_in[11];
    const float* comp_w   = (const float*)d_in[12];
    const float* comp_b   = (const float*)d_in[13];
    const float* vf_w     = (const float*)d_in[14];
    const float* vf_b     = (const float*)d_in[15];
    const float* fcout_w  = (const float*)d_in[16];
    const float* fcout_b  = (const float*)d_in[17];
    float* out = (float*)d_out;

    k1_conv_tokens<<<128, NTHR>>>(x, metadata, w_ih, b_ih, b_hh, comp_w, vf_w);
    k2_reduce<<<256, NTHR>>>(comp_b, vf_w);
    k3_abc<<<64, NTHR>>>(x, fc_w, fc_b, fc2_w, fc2_b, vf_w, vf_b);
    k4_attn<<<592, NTHR>>>();
    k5_epilogue<<<64, NTHR>>>(out, fc3_w, fc3_b, fcout_w, fcout_b);
}